// round 3
// baseline (speedup 1.0000x reference)
#include <cuda_runtime.h>

// GraphAppnp: fused sum-aggregation + APPNP alpha blend. HBM-bound streaming.
// Inputs: x[N,D], neighbor_agg[N,K,D], h[N,D], neighbor[N,K,D]
// Outputs (concat): x_out[N,D] then nbr_out[N,K,D]
// N=50000, K=32, D=64, ALPHA=0.1

#define ALPHA     0.1f
#define ONE_M_A   0.9f
#define KNBR      32
#define DDIM      64
#define D4        16          // D/4 float4 per row
#define KBATCH    8           // k-slices batched per load/store group

__global__ __launch_bounds__(256)
void appnp_fused_kernel(const float4* __restrict__ x,
                        const float4* __restrict__ nagg,
                        const float4* __restrict__ h,
                        const float4* __restrict__ nbr,
                        float4* __restrict__ out_x,
                        float4* __restrict__ out_nbr,
                        int n_nodes)
{
    int gtid = blockIdx.x * blockDim.x + threadIdx.x;
    int node = gtid >> 4;
    int d4   = gtid & 15;
    if (node >= n_nodes) return;

    size_t row_base = (size_t)node * (KNBR * D4) + d4;
    const float4* na_p  = nagg    + row_base;
    const float4* nb_p  = nbr     + row_base;
    float4*       out_p = out_nbr + row_base;

    size_t xr = (size_t)node * D4 + d4;
    float4 xv = x[xr];

    float4 acc = make_float4(0.f, 0.f, 0.f, 0.f);

    #pragma unroll
    for (int kb = 0; kb < KNBR / KBATCH; ++kb) {
        float4 a[KBATCH], b[KBATCH];

        // long same-array read burst #1: 8 contiguous k-rows of neighbor_agg
        #pragma unroll
        for (int j = 0; j < KBATCH; ++j)
            a[j] = __ldcs(na_p + (size_t)(kb * KBATCH + j) * D4);

        // long same-array read burst #2: 8 contiguous k-rows of neighbor
        #pragma unroll
        for (int j = 0; j < KBATCH; ++j)
            b[j] = __ldcs(nb_p + (size_t)(kb * KBATCH + j) * D4);

        // math: fold output into b regs to cap register pressure
        #pragma unroll
        for (int j = 0; j < KBATCH; ++j) {
            acc.x += a[j].x; acc.y += a[j].y; acc.z += a[j].z; acc.w += a[j].w;
            b[j].x = fmaf(ONE_M_A, a[j].x + xv.x, ALPHA * b[j].x);
            b[j].y = fmaf(ONE_M_A, a[j].y + xv.y, ALPHA * b[j].y);
            b[j].z = fmaf(ONE_M_A, a[j].z + xv.z, ALPHA * b[j].z);
            b[j].w = fmaf(ONE_M_A, a[j].w + xv.w, ALPHA * b[j].w);
        }

        // long write burst: 8 contiguous k-rows
        #pragma unroll
        for (int j = 0; j < KBATCH; ++j)
            __stcs(out_p + (size_t)(kb * KBATCH + j) * D4, b[j]);
    }

    float4 hv = h[xr];
    float4 xo;
    xo.x = fmaf(ONE_M_A, xv.x + acc.x, ALPHA * hv.x);
    xo.y = fmaf(ONE_M_A, xv.y + acc.y, ALPHA * hv.y);
    xo.z = fmaf(ONE_M_A, xv.z + acc.z, ALPHA * hv.z);
    xo.w = fmaf(ONE_M_A, xv.w + acc.w, ALPHA * hv.w);
    out_x[xr] = xo;
}

extern "C" void kernel_launch(void* const* d_in, const int* in_sizes, int n_in,
                              void* d_out, int out_size)
{
    const float4* x    = (const float4*)d_in[0];
    const float4* nagg = (const float4*)d_in[1];
    const float4* h    = (const float4*)d_in[2];
    const float4* nbr  = (const float4*)d_in[3];

    int n_nodes = in_sizes[0] / DDIM;

    float4* out_x   = (float4*)d_out;
    float4* out_nbr = (float4*)d_out + (size_t)n_nodes * D4;

    int total_threads = n_nodes * 16;
    int block = 256;
    int grid  = (total_threads + block - 1) / block;

    appnp_fused_kernel<<<grid, block>>>(x, nagg, h, nbr, out_x, out_nbr, n_nodes);
}

// round 4
// speedup vs baseline: 1.0335x; 1.0335x over previous
#include <cuda_runtime.h>

// GraphAppnp: fused sum-aggregation + APPNP alpha blend. HBM-bound streaming.
// One warp per node: lanes 0-15 -> row k (even), lanes 16-31 -> row k+1 (odd),
// so every warp-level load/store is one 512B fully-contiguous block.
// Inputs: x[N,D], neighbor_agg[N,K,D], h[N,D], neighbor[N,K,D]
// Outputs (concat): x_out[N,D] then nbr_out[N,K,D]
// N=50000, K=32, D=64, ALPHA=0.1

#define ALPHA     0.1f
#define ONE_M_A   0.9f
#define KNBR      32
#define DDIM      64
#define D4        16          // D/4 float4 per row
#define KBATCH    4           // k-pair steps batched per group
#define NSTEPS    (KNBR / 2)  // 16 pair-steps per node

__global__ __launch_bounds__(256, 3)
void appnp_fused_kernel(const float4* __restrict__ x,
                        const float4* __restrict__ nagg,
                        const float4* __restrict__ h,
                        const float4* __restrict__ nbr,
                        float4* __restrict__ out_x,
                        float4* __restrict__ out_nbr,
                        int n_nodes)
{
    int gtid  = blockIdx.x * blockDim.x + threadIdx.x;
    int node  = gtid >> 5;          // one warp per node
    int lane  = threadIdx.x & 31;
    int d4    = lane & 15;
    int khalf = lane >> 4;          // 0: even rows, 1: odd rows
    if (node >= n_nodes) return;

    // base points at (node, row=khalf, float4 d4); step stride = 2 rows
    size_t row_base = (size_t)node * (KNBR * D4) + (size_t)khalf * D4 + d4;
    const float4* na_p  = nagg    + row_base;
    const float4* nb_p  = nbr     + row_base;
    float4*       out_p = out_nbr + row_base;

    size_t xr = (size_t)node * D4 + d4;
    float4 xv = x[xr];              // lanes 0-15 / 16-31 load same 256B

    float4 acc = make_float4(0.f, 0.f, 0.f, 0.f);

    #pragma unroll
    for (int mb = 0; mb < NSTEPS / KBATCH; ++mb) {
        float4 a[KBATCH], b[KBATCH];

        #pragma unroll
        for (int j = 0; j < KBATCH; ++j) {
            size_t off = (size_t)(mb * KBATCH + j) * (2 * D4);
            a[j] = __ldcs(na_p + off);     // 512B contiguous per warp
            b[j] = __ldcs(nb_p + off);     // 512B contiguous per warp
        }

        #pragma unroll
        for (int j = 0; j < KBATCH; ++j) {
            acc.x += a[j].x; acc.y += a[j].y; acc.z += a[j].z; acc.w += a[j].w;
            b[j].x = fmaf(ONE_M_A, a[j].x + xv.x, ALPHA * b[j].x);
            b[j].y = fmaf(ONE_M_A, a[j].y + xv.y, ALPHA * b[j].y);
            b[j].z = fmaf(ONE_M_A, a[j].z + xv.z, ALPHA * b[j].z);
            b[j].w = fmaf(ONE_M_A, a[j].w + xv.w, ALPHA * b[j].w);
        }

        #pragma unroll
        for (int j = 0; j < KBATCH; ++j) {
            size_t off = (size_t)(mb * KBATCH + j) * (2 * D4);
            __stcs(out_p + off, b[j]);     // 512B contiguous per warp
        }
    }

    // combine even/odd-row partial sums across the two half-warps
    acc.x += __shfl_xor_sync(0xffffffffu, acc.x, 16);
    acc.y += __shfl_xor_sync(0xffffffffu, acc.y, 16);
    acc.z += __shfl_xor_sync(0xffffffffu, acc.z, 16);
    acc.w += __shfl_xor_sync(0xffffffffu, acc.w, 16);

    if (khalf == 0) {
        float4 hv = h[xr];
        float4 xo;
        xo.x = fmaf(ONE_M_A, xv.x + acc.x, ALPHA * hv.x);
        xo.y = fmaf(ONE_M_A, xv.y + acc.y, ALPHA * hv.y);
        xo.z = fmaf(ONE_M_A, xv.z + acc.z, ALPHA * hv.z);
        xo.w = fmaf(ONE_M_A, xv.w + acc.w, ALPHA * hv.w);
        out_x[xr] = xo;
    }
}

extern "C" void kernel_launch(void* const* d_in, const int* in_sizes, int n_in,
                              void* d_out, int out_size)
{
    const float4* x    = (const float4*)d_in[0];
    const float4* nagg = (const float4*)d_in[1];
    const float4* h    = (const float4*)d_in[2];
    const float4* nbr  = (const float4*)d_in[3];

    int n_nodes = in_sizes[0] / DDIM;

    float4* out_x   = (float4*)d_out;
    float4* out_nbr = (float4*)d_out + (size_t)n_nodes * D4;

    int total_threads = n_nodes * 32;     // one warp per node
    int block = 256;
    int grid  = (total_threads + block - 1) / block;

    appnp_fused_kernel<<<grid, block>>>(x, nagg, h, nbr, out_x, out_nbr, n_nodes);
}

// round 5
// speedup vs baseline: 1.0449x; 1.0111x over previous
#include <cuda_runtime.h>

// GraphAppnp: fused sum-aggregation + APPNP alpha blend. HBM-bound streaming.
// Co-streaming layout: each CTA (256 thr) handles 2 nodes; 4 warps share one
// node and sweep its 8KB region simultaneously (warp w: node w/4, k-quarter w%4).
// Within a warp: lanes 0-15 -> even row of pair, lanes 16-31 -> odd row, so
// every warp-level load/store is one 512B fully-contiguous block.
// Inputs: x[N,D], neighbor_agg[N,K,D], h[N,D], neighbor[N,K,D]
// Outputs (concat): x_out[N,D] then nbr_out[N,K,D]
// N=50000, K=32, D=64, ALPHA=0.1

#define ALPHA     0.1f
#define ONE_M_A   0.9f
#define KNBR      32
#define DDIM      64
#define D4        16          // D/4 float4 per row
#define PSTEPS    4           // pair-steps per warp (8 rows = quarter of K)

__global__ __launch_bounds__(256, 3)
void appnp_fused_kernel(const float4* __restrict__ x,
                        const float4* __restrict__ nagg,
                        const float4* __restrict__ h,
                        const float4* __restrict__ nbr,
                        float4* __restrict__ out_x,
                        float4* __restrict__ out_nbr,
                        int n_nodes)
{
    __shared__ float4 sacc[8][32];   // [warp][lane] partial sums (4KB)

    int wid   = threadIdx.x >> 5;    // 0..7
    int lane  = threadIdx.x & 31;
    int d4    = lane & 15;
    int khalf = lane >> 4;           // 0: even row of pair, 1: odd row
    int nloc  = wid >> 2;            // 0..1  node within CTA
    int kq    = wid & 3;             // 0..3  k-quarter within node

    int node = blockIdx.x * 2 + nloc;
    if (node >= n_nodes) return;     // n_nodes even (50000), whole CTA exits

    // warp base: (node, row = kq*8 + khalf, float4 d4); pair-step stride = 2 rows
    size_t row_base = (size_t)node * (KNBR * D4)
                    + (size_t)(kq * 8 + khalf) * D4 + d4;
    const float4* na_p  = nagg    + row_base;
    const float4* nb_p  = nbr     + row_base;
    float4*       out_p = out_nbr + row_base;

    size_t xr = (size_t)node * D4 + d4;
    float4 xv = x[xr];

    float4 a[PSTEPS], b[PSTEPS];

    #pragma unroll
    for (int j = 0; j < PSTEPS; ++j) {
        size_t off = (size_t)j * (2 * D4);
        a[j] = __ldcs(na_p + off);       // 512B contiguous per warp
        b[j] = __ldcs(nb_p + off);
    }

    float4 acc = make_float4(0.f, 0.f, 0.f, 0.f);

    #pragma unroll
    for (int j = 0; j < PSTEPS; ++j) {
        acc.x += a[j].x; acc.y += a[j].y; acc.z += a[j].z; acc.w += a[j].w;
        b[j].x = fmaf(ONE_M_A, a[j].x + xv.x, ALPHA * b[j].x);
        b[j].y = fmaf(ONE_M_A, a[j].y + xv.y, ALPHA * b[j].y);
        b[j].z = fmaf(ONE_M_A, a[j].z + xv.z, ALPHA * b[j].z);
        b[j].w = fmaf(ONE_M_A, a[j].w + xv.w, ALPHA * b[j].w);
    }

    #pragma unroll
    for (int j = 0; j < PSTEPS; ++j) {
        size_t off = (size_t)j * (2 * D4);
        __stcs(out_p + off, b[j]);       // 512B contiguous per warp
    }

    // cross-warp reduction of the per-node neighbor sum
    sacc[wid][lane] = acc;
    __syncthreads();

    // warp 0 finalizes node 0, warp 1 finalizes node 1 (lanes 0-15 active)
    if (wid < 2 && lane < 16) {
        int nl = wid;
        float4 s = make_float4(0.f, 0.f, 0.f, 0.f);
        #pragma unroll
        for (int j = 0; j < 4; ++j) {
            float4 v0 = sacc[nl * 4 + j][lane];
            float4 v1 = sacc[nl * 4 + j][lane + 16];
            s.x += v0.x + v1.x; s.y += v0.y + v1.y;
            s.z += v0.z + v1.z; s.w += v0.w + v1.w;
        }
        int fnode = blockIdx.x * 2 + nl;
        size_t fr = (size_t)fnode * D4 + lane;
        float4 xf = x[fr];
        float4 hv = h[fr];
        float4 xo;
        xo.x = fmaf(ONE_M_A, xf.x + s.x, ALPHA * hv.x);
        xo.y = fmaf(ONE_M_A, xf.y + s.y, ALPHA * hv.y);
        xo.z = fmaf(ONE_M_A, xf.z + s.z, ALPHA * hv.z);
        xo.w = fmaf(ONE_M_A, xf.w + s.w, ALPHA * hv.w);
        out_x[fr] = xo;
    }
}

extern "C" void kernel_launch(void* const* d_in, const int* in_sizes, int n_in,
                              void* d_out, int out_size)
{
    const float4* x    = (const float4*)d_in[0];
    const float4* nagg = (const float4*)d_in[1];
    const float4* h    = (const float4*)d_in[2];
    const float4* nbr  = (const float4*)d_in[3];

    int n_nodes = in_sizes[0] / DDIM;

    float4* out_x   = (float4*)d_out;
    float4* out_nbr = (float4*)d_out + (size_t)n_nodes * D4;

    int grid = (n_nodes + 1) / 2;    // 2 nodes per CTA

    appnp_fused_kernel<<<grid, 256>>>(x, nagg, h, nbr, out_x, out_nbr, n_nodes);
}